// round 14
// baseline (speedup 1.0000x reference)
#include <cuda_runtime.h>
#include <cuda_fp16.h>
#include <cstdint>

// ============================================================================
// Problem constants
// ============================================================================
#define NFEAT 4096
#define MROWS 1024
#define KTOP  41.0f
#define WSCALE 4096.0f          // 2^12, exact power of two
#define INV_WSCALE (1.0f/4096.0f)

// Scratch (device globals — allocation-free rule)
__device__ float g_alpha_topk[NFEAT];
__device__ __align__(128) __half g_Wh[(size_t)NFEAT * NFEAT];   // W * 2^12, fp16
__device__ __align__(128) __half g_Xh[(size_t)MROWS * NFEAT];   // x, fp16

// ============================================================================
// Small PTX helpers (base-arch safe: sm_80+ features only)
// ============================================================================
__device__ __forceinline__ uint32_t smem_to_u32(const void* p) {
    uint32_t a;
    asm("{ .reg .u64 t; cvta.to.shared.u64 t, %1; cvt.u32.u64 %0, t; }" : "=r"(a) : "l"(p));
    return a;
}
__device__ __forceinline__ void cp16(uint32_t dst_smem, const void* src) {
    asm volatile("cp.async.cg.shared.global [%0], [%1], 16;" :: "r"(dst_smem), "l"(src) : "memory");
}
#define CP_COMMIT() asm volatile("cp.async.commit_group;" ::: "memory")
#define CP_WAIT2()  asm volatile("cp.async.wait_group 2;"  ::: "memory")

__device__ __forceinline__ void mma16816(float* c, const uint32_t* a, const uint32_t* b) {
    asm volatile(
        "mma.sync.aligned.m16n8k16.row.col.f32.f16.f16.f32 "
        "{%0,%1,%2,%3}, {%4,%5,%6,%7}, {%8,%9}, {%0,%1,%2,%3};"
        : "+f"(c[0]), "+f"(c[1]), "+f"(c[2]), "+f"(c[3])
        : "r"(a[0]), "r"(a[1]), "r"(a[2]), "r"(a[3]), "r"(b[0]), "r"(b[1]));
}
__device__ __forceinline__ void ldmx4(uint32_t* r, uint32_t addr) {
    asm volatile("ldmatrix.sync.aligned.m8n8.x4.shared.b16 {%0,%1,%2,%3}, [%4];"
                 : "=r"(r[0]), "=r"(r[1]), "=r"(r[2]), "=r"(r[3]) : "r"(addr));
}

// ============================================================================
// Kernel 1: soft-top-k (collapsed Dykstra: S' = S + (k - sum clip)/n),
// single 256-thread block, early-break when converged.
// ============================================================================
__global__ void alpha_kernel(const float* __restrict__ alpha) {
    const int tid  = threadIdx.x;
    const int wid  = tid >> 5;
    const int lane = tid & 31;
    float y0[16];
#pragma unroll
    for (int j = 0; j < 16; j++) y0[j] = alpha[tid + j * 256] * 100.0f;  // /0.01

    __shared__ float wsum[2][8];
    float S = 0.f;

    for (int it = 0; it < 50; it++) {
        float local = 0.f;
#pragma unroll
        for (int j = 0; j < 16; j++) local += __saturatef(y0[j] + S);
#pragma unroll
        for (int o = 16; o > 0; o >>= 1) local += __shfl_xor_sync(0xffffffffu, local, o);
        if (lane == 0) wsum[it & 1][wid] = local;
        __syncthreads();
        float f = 0.f;
#pragma unroll
        for (int w = 0; w < 8; w++) f += wsum[it & 1][w];
        float dS = (KTOP - f) / (float)NFEAT;
        S += dS;
        if (fabsf(dS) < 1e-9f) break;    // uniform branch
    }
#pragma unroll
    for (int j = 0; j < 16; j++)
        g_alpha_topk[tid + j * 256] = __saturatef(y0[j] + S);
}

// ============================================================================
// Kernel 2: blocks [0,2048): Wh[r,c] = 2^12*a[i]*V[i,c], r=(i+c)%n via fp16
// smem diagonal transpose; blocks [2048,2560): x -> fp16.
// ============================================================================
#define TI 64
#define TC 128
#define STRH 136   // smem stride in halves; diag lane stride odd => conflict-free

__global__ __launch_bounds__(256) void build_w_kernel(const float* __restrict__ V,
                                                      const float* __restrict__ X) {
    const int b = blockIdx.x;
    const int tid = threadIdx.x;

    if (b >= 2048) {
        // x -> fp16: 512 blocks x 8192 floats
        const int base = (b - 2048) * 8192;
#pragma unroll
        for (int q = 0; q < 8; q++) {
            int i = base + q * 1024 + tid * 4;
            float4 v = *reinterpret_cast<const float4*>(X + i);
            __half2 h0 = __floats2half2_rn(v.x, v.y);
            __half2 h1 = __floats2half2_rn(v.z, v.w);
            uint2 packed;
            packed.x = *reinterpret_cast<uint32_t*>(&h0);
            packed.y = *reinterpret_cast<uint32_t*>(&h1);
            *reinterpret_cast<uint2*>(&g_Xh[i]) = packed;
        }
        return;
    }

    __shared__ __half tile[TI * STRH];
    const int i0 = (b >> 5) * TI;
    const int c0 = (b & 31) * TC;

#pragma unroll
    for (int pp = 0; pp < 8; pp++) {
        int idx = tid + pp * 256;        // 0..2047
        int il  = idx >> 5;              // 0..63
        int jq  = idx & 31;              // float4 index
        float a = g_alpha_topk[i0 + il] * WSCALE;
        float4 v = *reinterpret_cast<const float4*>(V + (size_t)(i0 + il) * NFEAT + c0 + jq * 4);
        __half2 h0 = __floats2half2_rn(a * v.x, a * v.y);
        __half2 h1 = __floats2half2_rn(a * v.z, a * v.w);
        uint2 packed;
        packed.x = *reinterpret_cast<uint32_t*>(&h0);
        packed.y = *reinterpret_cast<uint32_t*>(&h1);
        *reinterpret_cast<uint2*>(&tile[il * STRH + jq * 4]) = packed;
    }
    __syncthreads();

    const int row7 = tid / 36;           // 0..7 (7 invalid)
    const int p    = tid % 36;
    for (int base = 0; base < TI + TC - 1; base += 7) {
        int d = base + row7;
        if (row7 < 7 && d < TI + TC - 1) {
            int ccLo = max(0, d - (TI - 1));
            int ccHi = min(TC - 1, d);
            int cc = (ccLo & ~1) + 2 * p;
            if (cc <= ccHi) {
                bool v0 = (cc >= ccLo);
                bool v1 = (cc + 1 <= ccHi);
                int idx0 = v0 ? ((d - cc) * STRH + cc) : 0;
                int idx1 = v1 ? ((d - cc - 1) * STRH + cc + 1) : 0;
                __half h0 = v0 ? tile[idx0] : __half(0);
                __half h1 = v1 ? tile[idx1] : __half(0);
                int r = (i0 + c0 + d) & (NFEAT - 1);
                size_t o = (size_t)r * NFEAT + c0 + cc;
                if (v0 && v1) {
                    __half2 h = __halves2half2(h0, h1);
                    *reinterpret_cast<__half2*>(&g_Wh[o]) = h;
                } else if (v0) {
                    g_Wh[o] = h0;
                } else {
                    g_Wh[o + 1] = h1;
                }
            }
        }
    }
}

// ============================================================================
// Kernel 3: fp16 GEMM  out[1024,4096] = (Xh @ Wh^T) * 2^-12, fp32 accumulate.
//   BM=128, BN=256, 256 threads (8 warps, 2x4 of the 64x64 warp tile), grid
//   16x8 = 128 CTAs at 1 CTA/SM. NEW: 4-stage cp.async pipeline (192KB smem,
//   wait_group 2) — doubles copy-latency headroom per stage vs R13's 3-stage.
//   Issue interleaved into ks loop: barrier at stage s proves mma(s-1) done,
//   and issue(s+3) writes buffer (s+3)%4 == (s-1)%4 => safe.
// ============================================================================
#define BM 128
#define BN 256
#define NS (NFEAT / 64)                 // 64 K-stages
#define STAGE_A 16384                   // A: 128 rows x 128 B
#define STAGE_B 32768                   // B: 256 rows x 128 B
#define STAGE_BYTES (STAGE_A + STAGE_B) // 49152
#define NSTG 4
#define GEMM_SMEM (NSTG * STAGE_BYTES)  // 196608 B -> 1 CTA/SM

__device__ __forceinline__ void issue_A(int s, uint32_t sb, int m0, int tid) {
    if (s < NS) {
        const int buf = s % NSTG;
        const int k0h = s * 64;
#pragma unroll
        for (int p = 0; p < 4; p++) {
            int idx = tid + p * 256;     // 0..1023
            int row = idx >> 3, j = idx & 7;
            uint32_t off = (uint32_t)(row * 128 + j * 16);
            uint32_t sw  = off ^ (uint32_t)((row & 7) << 4);
            cp16(sb + buf * STAGE_BYTES + sw,
                 g_Xh + (size_t)(m0 + row) * NFEAT + k0h + j * 8);
        }
    }
}
__device__ __forceinline__ void issue_B(int s, uint32_t sb, int n0, int tid) {
    if (s < NS) {
        const int buf = s % NSTG;
        const int k0h = s * 64;
#pragma unroll
        for (int p = 0; p < 8; p++) {
            int idx = tid + p * 256;     // 0..2047
            int row = idx >> 3, j = idx & 7;
            uint32_t off = (uint32_t)(row * 128 + j * 16);
            uint32_t sw  = off ^ (uint32_t)((row & 7) << 4);
            cp16(sb + buf * STAGE_BYTES + STAGE_A + sw,
                 g_Wh + (size_t)(n0 + row) * NFEAT + k0h + j * 8);
        }
    }
}

__global__ __launch_bounds__(256, 1)
void gemm_kernel(float* __restrict__ OUT) {
    extern __shared__ char smem[];
    const uint32_t sb = smem_to_u32(smem);
    const int tid  = threadIdx.x;
    const int wid  = tid >> 5;
    const int lane = tid & 31;
    const int wm   = wid >> 2;           // 0..1 -> 64-row slab
    const int wn   = wid & 3;            // 0..3 -> 64-col slab
    const int m0 = blockIdx.y * BM;
    const int n0 = blockIdx.x * BN;

    float acc[32][4];
#pragma unroll
    for (int i = 0; i < 32; i++)
        acc[i][0] = acc[i][1] = acc[i][2] = acc[i][3] = 0.f;

    // ldmatrix per-lane addressing. lane = mat*8 + rowin.
    const int rowin = lane & 7;
    const int mat   = lane >> 3;
    const int rA = rowin + (mat & 1) * 8;
    const int cA = (mat >> 1) * 16;
    const int rB = rowin + (mat >> 1) * 8;
    const int cB = (mat & 1) * 16;

    uint32_t arow[4], brow[4], koffA[4], koffB[4];
#pragma unroll
    for (int mi = 0; mi < 4; mi++)
        arow[mi] = (uint32_t)((wm * 64 + mi * 16 + rA) * 128);
#pragma unroll
    for (int pr = 0; pr < 4; pr++)
        brow[pr] = (uint32_t)((wn * 64 + pr * 16 + rB) * 128) + STAGE_A;
#pragma unroll
    for (int ks = 0; ks < 4; ks++) {
        koffA[ks] = (uint32_t)((ks * 32 + cA) ^ (rowin << 4));
        koffB[ks] = (uint32_t)((ks * 32 + cB) ^ (rowin << 4));
    }

    issue_A(0, sb, m0, tid); issue_B(0, sb, n0, tid); CP_COMMIT();
    issue_A(1, sb, m0, tid); issue_B(1, sb, n0, tid); CP_COMMIT();
    issue_A(2, sb, m0, tid); issue_B(2, sb, n0, tid); CP_COMMIT();

    for (int s = 0; s < NS; s++) {
        CP_WAIT2();                      // group s complete (<=2 in flight)
        __syncthreads();
        const uint32_t stg = sb + (uint32_t)((s % NSTG) * STAGE_BYTES);
#pragma unroll
        for (int ks = 0; ks < 4; ks++) {
            uint32_t af[4][4], bf[8][2];
#pragma unroll
            for (int mi = 0; mi < 4; mi++)
                ldmx4(af[mi], stg + arow[mi] + koffA[ks]);
#pragma unroll
            for (int pr = 0; pr < 4; pr++) {
                uint32_t r[4];
                ldmx4(r, stg + brow[pr] + koffB[ks]);
                bf[pr * 2][0]     = r[0];
                bf[pr * 2][1]     = r[1];
                bf[pr * 2 + 1][0] = r[2];
                bf[pr * 2 + 1][1] = r[3];
            }
            if (ks == 0) issue_A(s + 3, sb, m0, tid);
            if (ks == 1) { issue_B(s + 3, sb, n0, tid); CP_COMMIT(); }
#pragma unroll
            for (int mi = 0; mi < 4; mi++)
#pragma unroll
                for (int ni = 0; ni < 8; ni++)
                    mma16816(acc[mi * 8 + ni], af[mi], bf[ni]);
        }
    }

    // Epilogue: undo 2^12 W scaling.
    const int t4 = lane >> 2, tq = lane & 3;
#pragma unroll
    for (int mi = 0; mi < 4; mi++) {
        int r = m0 + wm * 64 + mi * 16 + t4;
#pragma unroll
        for (int ni = 0; ni < 8; ni++) {
            int c = n0 + wn * 64 + ni * 8 + tq * 2;
            float* a = acc[mi * 8 + ni];
            float2 v0 = make_float2(a[0] * INV_WSCALE, a[1] * INV_WSCALE);
            float2 v1 = make_float2(a[2] * INV_WSCALE, a[3] * INV_WSCALE);
            *reinterpret_cast<float2*>(OUT + (size_t)r * NFEAT + c) = v0;
            *reinterpret_cast<float2*>(OUT + (size_t)(r + 8) * NFEAT + c) = v1;
        }
    }
}

// ============================================================================
// Launch: alpha -> build (W + xhalf) -> GEMM (serial schedule).
// ============================================================================
extern "C" void kernel_launch(void* const* d_in, const int* in_sizes, int n_in,
                              void* d_out, int out_size) {
    const float* x = nullptr;
    const float* V = nullptr;
    const float* alpha = nullptr;
    for (int i = 0; i < n_in; i++) {
        if (in_sizes[i] == NFEAT)               alpha = (const float*)d_in[i];
        else if (in_sizes[i] == MROWS * NFEAT)  x     = (const float*)d_in[i];
        else                                    V     = (const float*)d_in[i];
    }
    float* out = (float*)d_out;

    cudaFuncSetAttribute(gemm_kernel, cudaFuncAttributeMaxDynamicSharedMemorySize, GEMM_SMEM);

    alpha_kernel<<<1, 256>>>(alpha);
    build_w_kernel<<<2560, 256>>>(V, x);
    gemm_kernel<<<dim3(NFEAT / BN, MROWS / BM), 256, GEMM_SMEM>>>(out);
}

// round 17
// speedup vs baseline: 1.0361x; 1.0361x over previous
#include <cuda_runtime.h>
#include <cuda_fp16.h>
#include <cstdint>

// ============================================================================
// Problem constants
// ============================================================================
#define NFEAT 4096
#define MROWS 1024
#define KTOP  41.0f
#define WSCALE 4096.0f          // 2^12, exact power of two
#define INV_WSCALE (1.0f/4096.0f)

// Scratch (device globals — allocation-free rule)
__device__ float g_alpha_topk[NFEAT];
__device__ __align__(128) __half g_Wh[(size_t)NFEAT * NFEAT];   // W * 2^12, fp16
__device__ __align__(128) __half g_Xh[(size_t)MROWS * NFEAT];   // x, fp16

// ============================================================================
// Small PTX helpers (base-arch safe: sm_80+ features only)
// ============================================================================
__device__ __forceinline__ uint32_t smem_to_u32(const void* p) {
    uint32_t a;
    asm("{ .reg .u64 t; cvta.to.shared.u64 t, %1; cvt.u32.u64 %0, t; }" : "=r"(a) : "l"(p));
    return a;
}
__device__ __forceinline__ void cp16(uint32_t dst_smem, const void* src) {
    asm volatile("cp.async.cg.shared.global [%0], [%1], 16;" :: "r"(dst_smem), "l"(src) : "memory");
}
#define CP_COMMIT() asm volatile("cp.async.commit_group;" ::: "memory")
#define CP_WAIT0()  asm volatile("cp.async.wait_group 0;"  ::: "memory")

__device__ __forceinline__ void mma16816(float* c, const uint32_t* a, const uint32_t* b) {
    asm volatile(
        "mma.sync.aligned.m16n8k16.row.col.f32.f16.f16.f32 "
        "{%0,%1,%2,%3}, {%4,%5,%6,%7}, {%8,%9}, {%0,%1,%2,%3};"
        : "+f"(c[0]), "+f"(c[1]), "+f"(c[2]), "+f"(c[3])
        : "r"(a[0]), "r"(a[1]), "r"(a[2]), "r"(a[3]), "r"(b[0]), "r"(b[1]));
}
__device__ __forceinline__ void ldmx4(uint32_t* r, uint32_t addr) {
    asm volatile("ldmatrix.sync.aligned.m8n8.x4.shared.b16 {%0,%1,%2,%3}, [%4];"
                 : "=r"(r[0]), "=r"(r[1]), "=r"(r[2]), "=r"(r[3]) : "r"(addr));
}

// ============================================================================
// Kernel 1: soft-top-k (collapsed Dykstra: S' = S + (k - sum clip)/n),
// single 256-thread block, early-break when converged. (R13 verbatim.)
// ============================================================================
__global__ void alpha_kernel(const float* __restrict__ alpha) {
    const int tid  = threadIdx.x;
    const int wid  = tid >> 5;
    const int lane = tid & 31;
    float y0[16];
#pragma unroll
    for (int j = 0; j < 16; j++) y0[j] = alpha[tid + j * 256] * 100.0f;  // /0.01

    __shared__ float wsum[2][8];
    float S = 0.f;

    for (int it = 0; it < 50; it++) {
        float local = 0.f;
#pragma unroll
        for (int j = 0; j < 16; j++) local += __saturatef(y0[j] + S);
#pragma unroll
        for (int o = 16; o > 0; o >>= 1) local += __shfl_xor_sync(0xffffffffu, local, o);
        if (lane == 0) wsum[it & 1][wid] = local;
        __syncthreads();
        float f = 0.f;
#pragma unroll
        for (int w = 0; w < 8; w++) f += wsum[it & 1][w];
        float dS = (KTOP - f) / (float)NFEAT;
        S += dS;
        if (fabsf(dS) < 1e-9f) break;    // uniform branch
    }
#pragma unroll
    for (int j = 0; j < 16; j++)
        g_alpha_topk[tid + j * 256] = __saturatef(y0[j] + S);
}

// ============================================================================
// Kernel 2 (R13 verbatim): blocks [0,2048): Wh[r,c] = 2^12*a[i]*V[i,c],
// r=(i+c)%n via fp16 smem diagonal transpose; blocks [2048,2560): x -> fp16.
// ============================================================================
#define TI 64
#define TC 128
#define STRH 136   // smem stride in halves; diag lane stride odd => conflict-free

__global__ __launch_bounds__(256) void build_w_kernel(const float* __restrict__ V,
                                                      const float* __restrict__ X) {
    const int b = blockIdx.x;
    const int tid = threadIdx.x;

    if (b >= 2048) {
        // x -> fp16: 512 blocks x 8192 floats
        const int base = (b - 2048) * 8192;
#pragma unroll
        for (int q = 0; q < 8; q++) {
            int i = base + q * 1024 + tid * 4;
            float4 v = *reinterpret_cast<const float4*>(X + i);
            __half2 h0 = __floats2half2_rn(v.x, v.y);
            __half2 h1 = __floats2half2_rn(v.z, v.w);
            uint2 packed;
            packed.x = *reinterpret_cast<uint32_t*>(&h0);
            packed.y = *reinterpret_cast<uint32_t*>(&h1);
            *reinterpret_cast<uint2*>(&g_Xh[i]) = packed;
        }
        return;
    }

    __shared__ __half tile[TI * STRH];
    const int i0 = (b >> 5) * TI;
    const int c0 = (b & 31) * TC;

#pragma unroll
    for (int pp = 0; pp < 8; pp++) {
        int idx = tid + pp * 256;        // 0..2047
        int il  = idx >> 5;              // 0..63
        int jq  = idx & 31;              // float4 index
        float a = g_alpha_topk[i0 + il] * WSCALE;
        float4 v = *reinterpret_cast<const float4*>(V + (size_t)(i0 + il) * NFEAT + c0 + jq * 4);
        __half2 h0 = __floats2half2_rn(a * v.x, a * v.y);
        __half2 h1 = __floats2half2_rn(a * v.z, a * v.w);
        uint2 packed;
        packed.x = *reinterpret_cast<uint32_t*>(&h0);
        packed.y = *reinterpret_cast<uint32_t*>(&h1);
        *reinterpret_cast<uint2*>(&tile[il * STRH + jq * 4]) = packed;
    }
    __syncthreads();

    const int row7 = tid / 36;           // 0..7 (7 invalid)
    const int p    = tid % 36;
    for (int base = 0; base < TI + TC - 1; base += 7) {
        int d = base + row7;
        if (row7 < 7 && d < TI + TC - 1) {
            int ccLo = max(0, d - (TI - 1));
            int ccHi = min(TC - 1, d);
            int cc = (ccLo & ~1) + 2 * p;
            if (cc <= ccHi) {
                bool v0 = (cc >= ccLo);
                bool v1 = (cc + 1 <= ccHi);
                int idx0 = v0 ? ((d - cc) * STRH + cc) : 0;
                int idx1 = v1 ? ((d - cc - 1) * STRH + cc + 1) : 0;
                __half h0 = v0 ? tile[idx0] : __half(0);
                __half h1 = v1 ? tile[idx1] : __half(0);
                int r = (i0 + c0 + d) & (NFEAT - 1);
                size_t o = (size_t)r * NFEAT + c0 + cc;
                if (v0 && v1) {
                    __half2 h = __halves2half2(h0, h1);
                    *reinterpret_cast<__half2*>(&g_Wh[o]) = h;
                } else if (v0) {
                    g_Wh[o] = h0;
                } else {
                    g_Wh[o + 1] = h1;
                }
            }
        }
    }
}

// ============================================================================
// Kernel 3: fp16 GEMM  out[1024,4096] = (Xh @ Wh^T) * 2^-12, fp32 accumulate.
//   BM=128, BN=256, 256 threads (8 warps, 2x4 of the 64x64 warp tile), grid
//   16x8 = 128 CTAs at 1 CTA/SM. 4-sub-buffer ring (stage -> buf stage%4,
//   196KB) processed in PAIRS: one wait_group 0 + one __syncthreads per pair
//   (32 boundaries vs R13's 64). During pair (s, s+1) we issue stages s+2,
//   s+3 into buffers (s+2)%4, (s+3)%4 — both free: the barrier proves pair
//   (s-2, s-1) (same buffers) fully consumed, and neither is a live buffer.
//   Inner ks addressing / fragments / epilogue bit-identical to R13.
// ============================================================================
#define BM 128
#define BN 256
#define NSTAGES 64                      // BK=64 sub-stages
#define STAGE_A 16384                   // A: 128 rows x 128 B
#define STAGE_B 32768                   // B: 256 rows x 128 B
#define SUB_BYTES (STAGE_A + STAGE_B)   // 49152
#define GEMM_SMEM (4 * SUB_BYTES)       // 196608 B -> 1 CTA/SM

__device__ __forceinline__ void issue_A(int st, uint32_t sb, int m0, int tid) {
    if (st < NSTAGES) {
        const uint32_t base = (uint32_t)((st & 3) * SUB_BYTES);
        const int k0h = st * 64;
#pragma unroll
        for (int p = 0; p < 4; p++) {
            int idx = tid + p * 256;     // 0..1023
            int row = idx >> 3, j = idx & 7;
            uint32_t off = (uint32_t)(row * 128 + j * 16);
            uint32_t sw  = off ^ (uint32_t)((row & 7) << 4);
            cp16(sb + base + sw, g_Xh + (size_t)(m0 + row) * NFEAT + k0h + j * 8);
        }
    }
}
__device__ __forceinline__ void issue_B(int st, uint32_t sb, int n0, int tid) {
    if (st < NSTAGES) {
        const uint32_t base = (uint32_t)((st & 3) * SUB_BYTES) + STAGE_A;
        const int k0h = st * 64;
#pragma unroll
        for (int p = 0; p < 8; p++) {
            int idx = tid + p * 256;     // 0..2047
            int row = idx >> 3, j = idx & 7;
            uint32_t off = (uint32_t)(row * 128 + j * 16);
            uint32_t sw  = off ^ (uint32_t)((row & 7) << 4);
            cp16(sb + base + sw, g_Wh + (size_t)(n0 + row) * NFEAT + k0h + j * 8);
        }
    }
}

__global__ __launch_bounds__(256, 1)
void gemm_kernel(float* __restrict__ OUT) {
    extern __shared__ char smem[];
    const uint32_t sb = smem_to_u32(smem);
    const int tid  = threadIdx.x;
    const int wid  = tid >> 5;
    const int lane = tid & 31;
    const int wm   = wid >> 2;           // 0..1 -> 64-row slab
    const int wn   = wid & 3;            // 0..3 -> 64-col slab
    const int m0 = blockIdx.y * BM;
    const int n0 = blockIdx.x * BN;

    float acc[32][4];
#pragma unroll
    for (int i = 0; i < 32; i++)
        acc[i][0] = acc[i][1] = acc[i][2] = acc[i][3] = 0.f;

    // ldmatrix per-lane addressing. lane = mat*8 + rowin.
    const int rowin = lane & 7;
    const int mat   = lane >> 3;
    const int rA = rowin + (mat & 1) * 8;
    const int cA = (mat >> 1) * 16;
    const int rB = rowin + (mat >> 1) * 8;
    const int cB = (mat & 1) * 16;

    uint32_t arow[4], brow[4], koffA[4], koffB[4];
#pragma unroll
    for (int mi = 0; mi < 4; mi++)
        arow[mi] = (uint32_t)((wm * 64 + mi * 16 + rA) * 128);
#pragma unroll
    for (int pr = 0; pr < 4; pr++)
        brow[pr] = (uint32_t)((wn * 64 + pr * 16 + rB) * 128) + STAGE_A;
#pragma unroll
    for (int ks = 0; ks < 4; ks++) {
        koffA[ks] = (uint32_t)((ks * 32 + cA) ^ (rowin << 4));
        koffB[ks] = (uint32_t)((ks * 32 + cB) ^ (rowin << 4));
    }

    // Prologue: stages 0 and 1 in flight (one commit group).
    issue_A(0, sb, m0, tid); issue_B(0, sb, n0, tid);
    issue_A(1, sb, m0, tid); issue_B(1, sb, n0, tid);
    CP_COMMIT();

    for (int p2 = 0; p2 < NSTAGES / 2; p2++) {
        const int s = 2 * p2;
        CP_WAIT0();                      // previous pair's commit: stages s, s+1 resident
        __syncthreads();
#pragma unroll
        for (int ks8 = 0; ks8 < 8; ks8++) {
            const int st = s + (ks8 >> 2);
            const int ks = ks8 & 3;
            const uint32_t stg = sb + (uint32_t)((st & 3) * SUB_BYTES);
            uint32_t af[4][4], bf[8][2];
#pragma unroll
            for (int mi = 0; mi < 4; mi++)
                ldmx4(af[mi], stg + arow[mi] + koffA[ks]);
#pragma unroll
            for (int pr = 0; pr < 4; pr++) {
                uint32_t r[4];
                ldmx4(r, stg + brow[pr] + koffB[ks]);
                bf[pr * 2][0]     = r[0];
                bf[pr * 2][1]     = r[1];
                bf[pr * 2 + 1][0] = r[2];
                bf[pr * 2 + 1][1] = r[3];
            }
            // Issue next pair: buffers (s+2)&3, (s+3)&3 are free (!= s&3, (s+1)&3,
            // and the barrier above proved pair (s-2, s-1) fully consumed them).
            if (ks8 == 0) issue_A(s + 2, sb, m0, tid);
            if (ks8 == 1) issue_B(s + 2, sb, n0, tid);
            if (ks8 == 2) issue_A(s + 3, sb, m0, tid);
            if (ks8 == 3) { issue_B(s + 3, sb, n0, tid); CP_COMMIT(); }
#pragma unroll
            for (int mi = 0; mi < 4; mi++)
#pragma unroll
                for (int ni = 0; ni < 8; ni++)
                    mma16816(acc[mi * 8 + ni], af[mi], bf[ni]);
        }
    }

    // Epilogue: undo 2^12 W scaling.
    const int t4 = lane >> 2, tq = lane & 3;
#pragma unroll
    for (int mi = 0; mi < 4; mi++) {
        int r = m0 + wm * 64 + mi * 16 + t4;
#pragma unroll
        for (int ni = 0; ni < 8; ni++) {
            int c = n0 + wn * 64 + ni * 8 + tq * 2;
            float* a = acc[mi * 8 + ni];
            float2 v0 = make_float2(a[0] * INV_WSCALE, a[1] * INV_WSCALE);
            float2 v1 = make_float2(a[2] * INV_WSCALE, a[3] * INV_WSCALE);
            *reinterpret_cast<float2*>(OUT + (size_t)r * NFEAT + c) = v0;
            *reinterpret_cast<float2*>(OUT + (size_t)(r + 8) * NFEAT + c) = v1;
        }
    }
}

// ============================================================================
// Launch: alpha -> build (W + xhalf) -> GEMM (serial schedule).
// ============================================================================
extern "C" void kernel_launch(void* const* d_in, const int* in_sizes, int n_in,
                              void* d_out, int out_size) {
    const float* x = nullptr;
    const float* V = nullptr;
    const float* alpha = nullptr;
    for (int i = 0; i < n_in; i++) {
        if (in_sizes[i] == NFEAT)               alpha = (const float*)d_in[i];
        else if (in_sizes[i] == MROWS * NFEAT)  x     = (const float*)d_in[i];
        else                                    V     = (const float*)d_in[i];
    }
    float* out = (float*)d_out;

    cudaFuncSetAttribute(gemm_kernel, cudaFuncAttributeMaxDynamicSharedMemorySize, GEMM_SMEM);

    alpha_kernel<<<1, 256>>>(alpha);
    build_w_kernel<<<2560, 256>>>(V, x);
    gemm_kernel<<<dim3(NFEAT / BN, MROWS / BM), 256, GEMM_SMEM>>>(out);
}